// round 9
// baseline (speedup 1.0000x reference)
#include <cuda_runtime.h>
#include <cuda_bf16.h>
#include <cstdint>

// MissHitScatter: inputs [N=65536, D=1024] f32 -> out [P=4, N, D] f32.
// slice 0 = copy of input, slices 1..3 = zeros. 1.25 GiB total traffic.
//
// Champion structure (R3): contiguous per-block spans, batched __ldg loads
// (MLP=V) before __stwt streaming stores, copy blocks front-loaded then a
// long pure-write phase. R8: V=16 (64 KB span/block, 16384 blocks) to probe
// DRAM row locality; everything else identical to the 177.7us/91.1% champion.

#define V 16  // float4 per thread; block covers 256*V float4 = 64 KB

__global__ void __launch_bounds__(256) misshit_scatter_kernel(
    const float4* __restrict__ in, float4* __restrict__ out, size_t n4)
{
    size_t base = (size_t)blockIdx.x * (blockDim.x * V) + threadIdx.x;

    if (base + (size_t)(V - 1) * blockDim.x < n4) {
        // Pure copy block: batch all loads first (MLP=V), then stream stores.
        float4 v[V];
#pragma unroll
        for (int j = 0; j < V; j++)
            v[j] = __ldg(in + base + (size_t)j * blockDim.x);
#pragma unroll
        for (int j = 0; j < V; j++)
            __stwt(out + base + (size_t)j * blockDim.x, v[j]);
    } else if (base >= n4) {
        // Pure zero block: streaming stores only.
        const float4 z = make_float4(0.f, 0.f, 0.f, 0.f);
#pragma unroll
        for (int j = 0; j < V; j++) {
            size_t i = base + (size_t)j * blockDim.x;
            __stwt(out + i, z);
        }
    } else {
        // Straddles the copy/zero boundary (not taken for this shape:
        // n4 = 16Mi float4 is a multiple of 256*V = 4096).
        const float4 z = make_float4(0.f, 0.f, 0.f, 0.f);
#pragma unroll
        for (int j = 0; j < V; j++) {
            size_t i = base + (size_t)j * blockDim.x;
            float4 v = (i < n4) ? __ldg(in + i) : z;
            __stwt(out + i, v);
        }
    }
}

extern "C" void kernel_launch(void* const* d_in, const int* in_sizes, int n_in,
                              void* d_out, int out_size) {
    const size_t n_elems = (size_t)in_sizes[0];   // 65536 * 1024 floats
    const size_t n4 = n_elems / 4;                // float4 per slice
    const size_t total4 = n4 * 4;                 // float4 in full output

    const int threads = 256;
    const size_t per_block = (size_t)threads * V; // 4096 float4
    const int blocks = (int)((total4 + per_block - 1) / per_block);  // 16384

    misshit_scatter_kernel<<<blocks, threads>>>(
        (const float4*)d_in[0], (float4*)d_out, n4);
}

// round 12
// speedup vs baseline: 1.0199x; 1.0199x over previous
#include <cuda_runtime.h>
#include <cuda_bf16.h>
#include <cstdint>

// MissHitScatter: inputs [N=65536, D=1024] f32 -> out [P=4, N, D] f32.
// slice 0 = copy of input, slices 1..3 = zeros. 1.25 GiB total traffic.
//
// CONVERGED CHAMPION (R3/R7, reproduced twice): 8 x float4 per thread,
// contiguous per-block 32 KB spans, batched __ldg loads (MLP=8) before
// __stwt streaming stores, copy blocks front-loaded then a long pure-write
// phase at near-peak BW.
// Measured: 177.7 us kernel, 91.1% DRAM, 7.22 TB/s (90.2% of 8 TB/s spec).
// Tested & rejected: per-warp multi-stream stores (-10%), wave-interleaved
// block types (-9%), __ldcs (-18%), V=16 (-1.4%). Residual gap is HBM
// read/write turnaround + ramp — not kernel-addressable.

#define V 8  // float4 per thread

__global__ void __launch_bounds__(256) misshit_scatter_kernel(
    const float4* __restrict__ in, float4* __restrict__ out, size_t n4)
{
    // Each block covers a contiguous span of 256*V float4s; within each of the
    // V sub-iterations accesses are warp-coalesced (stride = blockDim).
    size_t base = (size_t)blockIdx.x * (blockDim.x * V) + threadIdx.x;

    if (base + (size_t)(V - 1) * blockDim.x < n4) {
        // Entirely inside the copy slice: batch all loads first (MLP=V).
        float4 v[V];
#pragma unroll
        for (int j = 0; j < V; j++)
            v[j] = __ldg(in + base + (size_t)j * blockDim.x);
#pragma unroll
        for (int j = 0; j < V; j++)
            __stwt(out + base + (size_t)j * blockDim.x, v[j]);
    } else if (base >= n4) {
        // Entirely inside the zero slices: pure streaming stores.
        const float4 z = make_float4(0.f, 0.f, 0.f, 0.f);
#pragma unroll
        for (int j = 0; j < V; j++) {
            size_t i = base + (size_t)j * blockDim.x;
            __stwt(out + i, z);
        }
    } else {
        // Straddles the copy/zero boundary (not taken for this shape:
        // n4 = 16Mi float4 is a multiple of 256*V = 2048).
        const float4 z = make_float4(0.f, 0.f, 0.f, 0.f);
#pragma unroll
        for (int j = 0; j < V; j++) {
            size_t i = base + (size_t)j * blockDim.x;
            float4 v = (i < n4) ? __ldg(in + i) : z;
            __stwt(out + i, v);
        }
    }
}

extern "C" void kernel_launch(void* const* d_in, const int* in_sizes, int n_in,
                              void* d_out, int out_size) {
    const size_t n_elems = (size_t)in_sizes[0];   // 65536 * 1024 floats
    const size_t n4 = n_elems / 4;                // float4 per slice
    const size_t total4 = n4 * 4;                 // float4 in full output

    const int threads = 256;
    const size_t per_block = (size_t)threads * V;
    const int blocks = (int)((total4 + per_block - 1) / per_block);  // 32768

    misshit_scatter_kernel<<<blocks, threads>>>(
        (const float4*)d_in[0], (float4*)d_out, n4);
}